// round 9
// baseline (speedup 1.0000x reference)
#include <cuda_runtime.h>

// Problem constants (fixed shapes)
#define NN   65536
#define BB   64
#define NPGc 1024
#define CCc  512
#define EEc  2097152
#define DEc  16
#define KKc  512
#define BKc  32768

// Output layout (float32, reference-return order)
#define OFF_XNEW  0LL
#define OFF_EI    16777216LL
#define OFF_EA    20971520LL
#define OFF_MASK  54525952LL
#define OFF_BATCH 56623104LL
#define OFF_PERM  56655872LL

// Scratch. Invariant: g_degE is zero at entry and restored each replay.
// g_scoreD is rewritten fresh by k_dinv each replay before scatter adds.
__device__ float  g_h[NN];        // h = x@W (raw)
__device__ float2 g_hd[NN];       // (h, dinv) packed
__device__ double g_scoreD[NN];   // order-independent (double) score accumulator
__device__ float  g_score[NN];    // final float score
__device__ int    g_degE[NN];
__device__ int    g_newidx[NN];
__device__ int    g_perm[BKc];

#define PROJ_BLOCKS 8192
#define DEG_BLOCKS  1024        // (E/8)/256

// K1: fused  h = x@W (warp/row)  ||  in-degree atomics (8 edges/thread)
__global__ void k_proj_deg(const float* __restrict__ x, const float* __restrict__ W,
                           const int* __restrict__ dst) {
    if (blockIdx.x < PROJ_BLOCKS) {
        int warp = (blockIdx.x * blockDim.x + threadIdx.x) >> 5;
        int lane = threadIdx.x & 31;
        const float4* xr = (const float4*)(x + (size_t)warp * CCc);
        const float4* w4 = (const float4*)W;
        float s = 0.f;
#pragma unroll
        for (int i = 0; i < 4; i++) {
            float4 a = xr[lane + i * 32];
            float4 w = w4[lane + i * 32];
            s += a.x * w.x + a.y * w.y + a.z * w.z + a.w * w.w;
        }
#pragma unroll
        for (int o = 16; o; o >>= 1) s += __shfl_down_sync(0xffffffffu, s, o);
        if (lane == 0) {
            g_h[warp] = s;
            g_newidx[warp] = -1;
        }
    } else {
        int idx = (blockIdx.x - PROJ_BLOCKS) * 256 + threadIdx.x;   // < E/8
        int4 da = ((const int4*)dst)[2 * idx];
        int4 db = ((const int4*)dst)[2 * idx + 1];
        atomicAdd(&g_degE[da.x], 1);
        atomicAdd(&g_degE[da.y], 1);
        atomicAdd(&g_degE[da.z], 1);
        atomicAdd(&g_degE[da.w], 1);
        atomicAdd(&g_degE[db.x], 1);
        atomicAdd(&g_degE[db.y], 1);
        atomicAdd(&g_degE[db.z], 1);
        atomicAdd(&g_degE[db.w], 1);
    }
}

// K2: dinv = rsqrt(1+degE); pack (h,dinv); scoreD = h*(dinv*dinv); reset degE
__global__ void k_dinv() {
    int i = blockIdx.x * blockDim.x + threadIdx.x;
    float dv = rsqrtf(1.0f + (float)g_degE[i]);
    float h = g_h[i];
    g_hd[i] = make_float2(h, dv);
    g_scoreD[i] = (double)__fmul_rn(h, __fmul_rn(dv, dv));
    g_degE[i] = 0;
}

// K3: scoreD[d] += (double)( h[s] * (dinv[s]*dinv[d]) )   — 8 edges/thread.
__global__ void k_scatter(const int* __restrict__ src, const int* __restrict__ dst) {
    int idx = blockIdx.x * blockDim.x + threadIdx.x;    // < E/8
    int4 sa = ((const int4*)src)[2 * idx];
    int4 sb = ((const int4*)src)[2 * idx + 1];
    int4 da = ((const int4*)dst)[2 * idx];
    int4 db = ((const int4*)dst)[2 * idx + 1];
    float2 p0 = g_hd[sa.x], p1 = g_hd[sa.y], p2 = g_hd[sa.z], p3 = g_hd[sa.w];
    float2 p4 = g_hd[sb.x], p5 = g_hd[sb.y], p6 = g_hd[sb.z], p7 = g_hd[sb.w];
    float d0 = g_hd[da.x].y, d1 = g_hd[da.y].y, d2 = g_hd[da.z].y, d3 = g_hd[da.w].y;
    float d4 = g_hd[db.x].y, d5 = g_hd[db.y].y, d6 = g_hd[db.z].y, d7 = g_hd[db.w].y;
    atomicAdd(&g_scoreD[da.x], (double)__fmul_rn(p0.x, __fmul_rn(p0.y, d0)));
    atomicAdd(&g_scoreD[da.y], (double)__fmul_rn(p1.x, __fmul_rn(p1.y, d1)));
    atomicAdd(&g_scoreD[da.z], (double)__fmul_rn(p2.x, __fmul_rn(p2.y, d2)));
    atomicAdd(&g_scoreD[da.w], (double)__fmul_rn(p3.x, __fmul_rn(p3.y, d3)));
    atomicAdd(&g_scoreD[db.x], (double)__fmul_rn(p4.x, __fmul_rn(p4.y, d4)));
    atomicAdd(&g_scoreD[db.y], (double)__fmul_rn(p5.x, __fmul_rn(p5.y, d5)));
    atomicAdd(&g_scoreD[db.z], (double)__fmul_rn(p6.x, __fmul_rn(p6.y, d6)));
    atomicAdd(&g_scoreD[db.w], (double)__fmul_rn(p7.x, __fmul_rn(p7.y, d7)));
}

// K4: per-graph top-k via register-blocked bitonic sort.
// 128 threads x 8 elements/thread. Element i = t*8 + e.
//   j in {1,2,4}   : in-register compare-exchange
//   j in {8..128}  : in-warp shfl_xor(j>>3), ILP=8
//   j in {256,512} : shared-memory exchange (padded, 2 barriers each)
__global__ void k_topk(const float* __restrict__ b, float* __restrict__ out) {
    __shared__ unsigned long long sh[NPGc + (NPGc >> 3)];
#define SPAD(i) ((i) + ((i) >> 3))
    int g = blockIdx.x, t = threadIdx.x;      // t in [0,128)
    float bb = b[0];
    int base = g * NPGc + t * 8;

    // load 8 scores (double) -> float score -> keys
    unsigned long long v[8];
    float scv[8];
#pragma unroll
    for (int q = 0; q < 4; q++) {
        double2 d2 = ((const double2*)(g_scoreD + base))[q];
        scv[2 * q]     = (float)d2.x + bb;
        scv[2 * q + 1] = (float)d2.y + bb;
    }
    // persist float scores for the epilogue (two float4 stores)
    ((float4*)(g_score + base))[0] = make_float4(scv[0], scv[1], scv[2], scv[3]);
    ((float4*)(g_score + base))[1] = make_float4(scv[4], scv[5], scv[6], scv[7]);
#pragma unroll
    for (int e = 0; e < 8; e++) {
        unsigned int u = __float_as_uint(scv[e]);
        u = (u & 0x80000000u) ? ~u : (u | 0x80000000u);
        u = ~u;                                // ascending key == descending score
        v[e] = ((unsigned long long)u << 32) | (unsigned int)(t * 8 + e);
    }

#pragma unroll
    for (int k = 2; k <= NPGc; k <<= 1) {
#pragma unroll
        for (int j = k >> 1; j >= 1; j >>= 1) {
            if (j >= 256) {
                // cross-warp via shared
#pragma unroll
                for (int e = 0; e < 8; e++) {
                    int i = t * 8 + e;
                    sh[SPAD(i)] = v[e];
                }
                __syncthreads();
                bool up = ((t & (k >> 3)) == 0);
                bool keepmin = (up == ((t & (j >> 3)) == 0));
#pragma unroll
                for (int e = 0; e < 8; e++) {
                    int ip = (t * 8 + e) ^ j;
                    unsigned long long o = sh[SPAD(ip)];
                    v[e] = keepmin ? (o < v[e] ? o : v[e]) : (o > v[e] ? o : v[e]);
                }
                __syncthreads();
            } else if (j >= 8) {
                // in-warp shuffle
                bool up = ((t & (k >> 3)) == 0);
                bool keepmin = (up == ((t & (j >> 3)) == 0));
#pragma unroll
                for (int e = 0; e < 8; e++) {
                    unsigned long long o = __shfl_xor_sync(0xffffffffu, v[e], j >> 3);
                    v[e] = keepmin ? (o < v[e] ? o : v[e]) : (o > v[e] ? o : v[e]);
                }
            } else {
                // in-register
#pragma unroll
                for (int e = 0; e < 8; e++) {
                    if ((e & j) == 0) {
                        int e2 = e | j;
                        bool up = (((t * 8 + e) & k) == 0);
                        unsigned long long a = v[e], c = v[e2];
                        if ((a > c) == up) { v[e] = c; v[e2] = a; }
                    }
                }
            }
        }
    }

    // threads t<64 hold the top-512 elements (i = t*8+e < 512), sorted
    if (t < (KKc / 8)) {
#pragma unroll
        for (int e = 0; e < 8; e++) {
            int li = (int)(v[e] & 0xFFFFFFFFu);
            int n2 = g * NPGc + li;
            int p = g * KKc + t * 8 + e;
            g_perm[p] = n2;
            g_newidx[n2] = p;
            out[OFF_PERM + p]  = (float)n2;
            out[OFF_BATCH + p] = (float)g;
        }
    }
#undef SPAD
}

#define GATHER_BLOCKS 16384
#define EDGE_BLOCKS   2048      // 1024 edges/block, 4 edges/thread (int4)

// K5: fused epilogue: x_new gather || ei remap (int4/float4) + mask + masked ea copy
__global__ void k_epilogue(const float* __restrict__ x,
                           const int* __restrict__ src, const int* __restrict__ dst,
                           const float* __restrict__ ea, float* __restrict__ out) {
    if (blockIdx.x < GATHER_BLOCKS) {
        int row  = blockIdx.x * 2 + (threadIdx.x >> 7);
        int col4 = threadIdx.x & 127;
        int srcn = g_perm[row];
        float sc = tanhf(g_score[srcn]);
        float4 v = ((const float4*)(x + (size_t)srcn * CCc))[col4];
        v.x *= sc; v.y *= sc; v.z *= sc; v.w *= sc;
        ((float4*)(out + OFF_XNEW + (size_t)row * CCc))[col4] = v;
    } else {
        int e4   = (blockIdx.x - GATHER_BLOCKS) * 256 + threadIdx.x;   // < E/4
        int lane = threadIdx.x & 31;
        int4 s4 = ((const int4*)src)[e4];
        int4 d4 = ((const int4*)dst)[e4];
        int ns0 = g_newidx[s4.x], ns1 = g_newidx[s4.y], ns2 = g_newidx[s4.z], ns3 = g_newidx[s4.w];
        int nd0 = g_newidx[d4.x], nd1 = g_newidx[d4.y], nd2 = g_newidx[d4.z], nd3 = g_newidx[d4.w];
        bool m0 = (ns0 >= 0) && (nd0 >= 0);
        bool m1 = (ns1 >= 0) && (nd1 >= 0);
        bool m2 = (ns2 >= 0) && (nd2 >= 0);
        bool m3 = (ns3 >= 0) && (nd3 >= 0);
        float4 eis = make_float4(m0 ? (float)ns0 : -1.f, m1 ? (float)ns1 : -1.f,
                                 m2 ? (float)ns2 : -1.f, m3 ? (float)ns3 : -1.f);
        float4 eid = make_float4(m0 ? (float)nd0 : -1.f, m1 ? (float)nd1 : -1.f,
                                 m2 ? (float)nd2 : -1.f, m3 ? (float)nd3 : -1.f);
        float4 msk = make_float4(m0 ? 1.f : 0.f, m1 ? 1.f : 0.f,
                                 m2 ? 1.f : 0.f, m3 ? 1.f : 0.f);
        ((float4*)(out + OFF_EI))[e4]       = eis;
        ((float4*)(out + OFF_EI + EEc))[e4] = eid;
        ((float4*)(out + OFF_MASK))[e4]     = msk;
        unsigned mm = ((unsigned)m0) | ((unsigned)m1 << 1) | ((unsigned)m2 << 2) | ((unsigned)m3 << 3);
        long warpQuadBase = (long)(e4 - lane) * 16;
        const float4* eav = (const float4*)ea;
        float4* outv = (float4*)(out + OFF_EA);
#pragma unroll
        for (int half = 0; half < 4; half++) {
            int eIdx = half * 32 + lane;
            unsigned srcbits = __shfl_sync(0xffffffffu, mm, eIdx >> 2);
            bool me = (srcbits >> (eIdx & 3)) & 1u;
            unsigned bmask = __ballot_sync(0xffffffffu, me);
#pragma unroll
            for (int it = 0; it < 4; it++) {
                int tt = it * 32 + lane;
                bool keep = (bmask >> (tt >> 2)) & 1u;
                long o = warpQuadBase + (long)half * 128 + tt;
                float4 vv = make_float4(0.f, 0.f, 0.f, 0.f);
                if (keep) vv = eav[o];
                outv[o] = vv;
            }
        }
    }
}

extern "C" void kernel_launch(void* const* d_in, const int* in_sizes, int n_in,
                              void* d_out, int out_size) {
    const float* x   = (const float*)d_in[0];
    const int*   ei  = (const int*)d_in[1];
    const float* ea  = (const float*)d_in[2];
    const float* W   = (const float*)d_in[4];
    const float* b   = (const float*)d_in[5];
    float* out = (float*)d_out;

    const int* src = ei;
    const int* dst = ei + EEc;

    k_proj_deg<<<PROJ_BLOCKS + DEG_BLOCKS, 256>>>(x, W, dst);
    k_dinv    <<<NN / 256, 256>>>();
    k_scatter <<<(EEc / 8) / 256, 256>>>(src, dst);
    k_topk    <<<BB, 128>>>(b, out);
    k_epilogue<<<GATHER_BLOCKS + EDGE_BLOCKS, 256>>>(x, src, dst, ea, out);
}

// round 10
// speedup vs baseline: 1.0402x; 1.0402x over previous
#include <cuda_runtime.h>

// Problem constants (fixed shapes)
#define NN   65536
#define BB   64
#define NPGc 1024
#define CCc  512
#define EEc  2097152
#define DEc  16
#define KKc  512
#define BKc  32768

// Output layout (float32, reference-return order)
#define OFF_XNEW  0LL
#define OFF_EI    16777216LL
#define OFF_EA    20971520LL
#define OFF_MASK  54525952LL
#define OFF_BATCH 56623104LL
#define OFF_PERM  56655872LL

// Scratch. Replay invariants: g_degE and g_scoreD are zero at kernel_launch
// entry (zero-init on first call; k_topk resets both at the end of each replay).
__device__ float  g_h[NN];        // h = x@W (rewritten each replay by proj)
__device__ double g_scoreD[NN];   // order-independent f64 edge-term accumulator
__device__ float  g_score[NN];    // final float score (written by k_topk)
__device__ int    g_degE[NN];
__device__ int    g_newidx[NN];
__device__ int    g_perm[BKc];

#define PROJ_BLOCKS 8192
#define DEG_BLOCKS  1024        // (E/8)/256

// K1: fused  h = x@W (warp/row)  ||  in-degree atomics (8 edges/thread)
__global__ void k_proj_deg(const float* __restrict__ x, const float* __restrict__ W,
                           const int* __restrict__ dst) {
    if (blockIdx.x < PROJ_BLOCKS) {
        int warp = (blockIdx.x * blockDim.x + threadIdx.x) >> 5;
        int lane = threadIdx.x & 31;
        const float4* xr = (const float4*)(x + (size_t)warp * CCc);
        const float4* w4 = (const float4*)W;
        float s = 0.f;
#pragma unroll
        for (int i = 0; i < 4; i++) {
            float4 a = xr[lane + i * 32];
            float4 w = w4[lane + i * 32];
            s += a.x * w.x + a.y * w.y + a.z * w.z + a.w * w.w;
        }
#pragma unroll
        for (int o = 16; o; o >>= 1) s += __shfl_down_sync(0xffffffffu, s, o);
        if (lane == 0) {
            g_h[warp] = s;
            g_newidx[warp] = -1;
        }
    } else {
        int idx = (blockIdx.x - PROJ_BLOCKS) * 256 + threadIdx.x;   // < E/8
        int4 da = ((const int4*)dst)[2 * idx];
        int4 db = ((const int4*)dst)[2 * idx + 1];
        atomicAdd(&g_degE[da.x], 1);
        atomicAdd(&g_degE[da.y], 1);
        atomicAdd(&g_degE[da.z], 1);
        atomicAdd(&g_degE[da.w], 1);
        atomicAdd(&g_degE[db.x], 1);
        atomicAdd(&g_degE[db.y], 1);
        atomicAdd(&g_degE[db.z], 1);
        atomicAdd(&g_degE[db.w], 1);
    }
}

// K2: scatter with shared (h, dinv) staging.
// 8 blocks per graph, 4096 edges per block, 16 edges per thread.
// Edges never cross graphs, so each block stages its own graph's 1024 nodes.
// Per-term float rounding matches the reference EXACTLY:
//   term = fmul(h[s], fmul(dinv[s], dinv[d])),  dinv = rsqrtf(1 + degE)
// f64 global accumulation -> order-independent -> deterministic ranking.
__global__ void k_scatter(const int* __restrict__ src, const int* __restrict__ dst) {
    __shared__ float2 hd[NPGc];
    int g = blockIdx.x >> 3, slice = blockIdx.x & 7;
    int t = threadIdx.x;                    // 256 threads
    int nb = g * NPGc;

    float4 hv = ((const float4*)(g_h + nb))[t];
    int4   dg = ((const int4*)(g_degE + nb))[t];
    hd[4 * t + 0] = make_float2(hv.x, rsqrtf(1.0f + (float)dg.x));
    hd[4 * t + 1] = make_float2(hv.y, rsqrtf(1.0f + (float)dg.y));
    hd[4 * t + 2] = make_float2(hv.z, rsqrtf(1.0f + (float)dg.z));
    hd[4 * t + 3] = make_float2(hv.w, rsqrtf(1.0f + (float)dg.w));
    __syncthreads();

    long ebase = (long)g * (NPGc * 32) + (long)slice * 4096;  // 4096-aligned
    const int4* sp = (const int4*)(src + ebase);
    const int4* dp = (const int4*)(dst + ebase);
#pragma unroll
    for (int r = 0; r < 4; r++) {
        int q = r * 256 + t;                // coalesced quad index, < 1024
        int4 s4 = sp[q];
        int4 d4 = dp[q];
        float2 ps0 = hd[s4.x & (NPGc - 1)], ps1 = hd[s4.y & (NPGc - 1)];
        float2 ps2 = hd[s4.z & (NPGc - 1)], ps3 = hd[s4.w & (NPGc - 1)];
        float dd0 = hd[d4.x & (NPGc - 1)].y, dd1 = hd[d4.y & (NPGc - 1)].y;
        float dd2 = hd[d4.z & (NPGc - 1)].y, dd3 = hd[d4.w & (NPGc - 1)].y;
        atomicAdd(&g_scoreD[d4.x], (double)__fmul_rn(ps0.x, __fmul_rn(ps0.y, dd0)));
        atomicAdd(&g_scoreD[d4.y], (double)__fmul_rn(ps1.x, __fmul_rn(ps1.y, dd1)));
        atomicAdd(&g_scoreD[d4.z], (double)__fmul_rn(ps2.x, __fmul_rn(ps2.y, dd2)));
        atomicAdd(&g_scoreD[d4.w], (double)__fmul_rn(ps3.x, __fmul_rn(ps3.y, dd3)));
    }
}

// K3: self-term + top-k (register-blocked bitonic, 128 threads x 8 elems),
// then reset scoreD and degE for the next replay.
__global__ void k_topk(const float* __restrict__ b, float* __restrict__ out) {
    __shared__ unsigned long long sh[NPGc + (NPGc >> 3)];
#define SPAD(i) ((i) + ((i) >> 3))
    int g = blockIdx.x, t = threadIdx.x;      // t in [0,128)
    float bb = b[0];
    int base = g * NPGc + t * 8;

    float4 h0 = ((const float4*)(g_h + base))[0];
    float4 h1 = ((const float4*)(g_h + base))[1];
    int4   e0 = ((const int4*)(g_degE + base))[0];
    int4   e1 = ((const int4*)(g_degE + base))[1];
    float hv[8] = {h0.x, h0.y, h0.z, h0.w, h1.x, h1.y, h1.z, h1.w};
    int   ev[8] = {e0.x, e0.y, e0.z, e0.w, e1.x, e1.y, e1.z, e1.w};

    unsigned long long v[8];
    float scv[8];
#pragma unroll
    for (int q = 0; q < 4; q++) {
        double2 d2 = ((const double2*)(g_scoreD + base))[q];
        float dva = rsqrtf(1.0f + (float)ev[2 * q]);
        float dvb = rsqrtf(1.0f + (float)ev[2 * q + 1]);
        double sa = (double)__fmul_rn(hv[2 * q],     __fmul_rn(dva, dva));
        double sb = (double)__fmul_rn(hv[2 * q + 1], __fmul_rn(dvb, dvb));
        scv[2 * q]     = (float)(d2.x + sa) + bb;
        scv[2 * q + 1] = (float)(d2.y + sb) + bb;
    }
    // reset accumulators for next replay
    ((double2*)(g_scoreD + base))[0] = make_double2(0.0, 0.0);
    ((double2*)(g_scoreD + base))[1] = make_double2(0.0, 0.0);
    ((double2*)(g_scoreD + base))[2] = make_double2(0.0, 0.0);
    ((double2*)(g_scoreD + base))[3] = make_double2(0.0, 0.0);
    ((int4*)(g_degE + base))[0] = make_int4(0, 0, 0, 0);
    ((int4*)(g_degE + base))[1] = make_int4(0, 0, 0, 0);
    // persist float scores for the epilogue
    ((float4*)(g_score + base))[0] = make_float4(scv[0], scv[1], scv[2], scv[3]);
    ((float4*)(g_score + base))[1] = make_float4(scv[4], scv[5], scv[6], scv[7]);

#pragma unroll
    for (int e = 0; e < 8; e++) {
        unsigned int u = __float_as_uint(scv[e]);
        u = (u & 0x80000000u) ? ~u : (u | 0x80000000u);
        u = ~u;                                // ascending key == descending score
        v[e] = ((unsigned long long)u << 32) | (unsigned int)(t * 8 + e);
    }

#pragma unroll
    for (int k = 2; k <= NPGc; k <<= 1) {
#pragma unroll
        for (int j = k >> 1; j >= 1; j >>= 1) {
            if (j >= 256) {
#pragma unroll
                for (int e = 0; e < 8; e++) sh[SPAD(t * 8 + e)] = v[e];
                __syncthreads();
                bool up = ((t & (k >> 3)) == 0);
                bool keepmin = (up == ((t & (j >> 3)) == 0));
#pragma unroll
                for (int e = 0; e < 8; e++) {
                    unsigned long long o = sh[SPAD((t * 8 + e) ^ j)];
                    v[e] = keepmin ? (o < v[e] ? o : v[e]) : (o > v[e] ? o : v[e]);
                }
                __syncthreads();
            } else if (j >= 8) {
                bool up = ((t & (k >> 3)) == 0);
                bool keepmin = (up == ((t & (j >> 3)) == 0));
#pragma unroll
                for (int e = 0; e < 8; e++) {
                    unsigned long long o = __shfl_xor_sync(0xffffffffu, v[e], j >> 3);
                    v[e] = keepmin ? (o < v[e] ? o : v[e]) : (o > v[e] ? o : v[e]);
                }
            } else {
#pragma unroll
                for (int e = 0; e < 8; e++) {
                    if ((e & j) == 0) {
                        int e2 = e | j;
                        bool up = (((t * 8 + e) & k) == 0);
                        unsigned long long a = v[e], c = v[e2];
                        if ((a > c) == up) { v[e] = c; v[e2] = a; }
                    }
                }
            }
        }
    }

    if (t < (KKc / 8)) {
#pragma unroll
        for (int e = 0; e < 8; e++) {
            int li = (int)(v[e] & 0xFFFFFFFFu);
            int n2 = g * NPGc + li;
            int p = g * KKc + t * 8 + e;
            g_perm[p] = n2;
            g_newidx[n2] = p;
            out[OFF_PERM + p]  = (float)n2;
            out[OFF_BATCH + p] = (float)g;
        }
    }
#undef SPAD
}

#define GATHER_BLOCKS 16384
#define EDGE_BLOCKS   2048      // 1024 edges/block, 4 edges/thread (int4)

// K4: fused epilogue: x_new gather || ei remap (int4/float4) + mask + masked ea copy
__global__ void k_epilogue(const float* __restrict__ x,
                           const int* __restrict__ src, const int* __restrict__ dst,
                           const float* __restrict__ ea, float* __restrict__ out) {
    if (blockIdx.x < GATHER_BLOCKS) {
        int row  = blockIdx.x * 2 + (threadIdx.x >> 7);
        int col4 = threadIdx.x & 127;
        int srcn = g_perm[row];
        float sc = tanhf(g_score[srcn]);
        float4 v = ((const float4*)(x + (size_t)srcn * CCc))[col4];
        v.x *= sc; v.y *= sc; v.z *= sc; v.w *= sc;
        ((float4*)(out + OFF_XNEW + (size_t)row * CCc))[col4] = v;
    } else {
        int e4   = (blockIdx.x - GATHER_BLOCKS) * 256 + threadIdx.x;   // < E/4
        int lane = threadIdx.x & 31;
        int4 s4 = ((const int4*)src)[e4];
        int4 d4 = ((const int4*)dst)[e4];
        int ns0 = g_newidx[s4.x], ns1 = g_newidx[s4.y], ns2 = g_newidx[s4.z], ns3 = g_newidx[s4.w];
        int nd0 = g_newidx[d4.x], nd1 = g_newidx[d4.y], nd2 = g_newidx[d4.z], nd3 = g_newidx[d4.w];
        bool m0 = (ns0 >= 0) && (nd0 >= 0);
        bool m1 = (ns1 >= 0) && (nd1 >= 0);
        bool m2 = (ns2 >= 0) && (nd2 >= 0);
        bool m3 = (ns3 >= 0) && (nd3 >= 0);
        float4 eis = make_float4(m0 ? (float)ns0 : -1.f, m1 ? (float)ns1 : -1.f,
                                 m2 ? (float)ns2 : -1.f, m3 ? (float)ns3 : -1.f);
        float4 eid = make_float4(m0 ? (float)nd0 : -1.f, m1 ? (float)nd1 : -1.f,
                                 m2 ? (float)nd2 : -1.f, m3 ? (float)nd3 : -1.f);
        float4 msk = make_float4(m0 ? 1.f : 0.f, m1 ? 1.f : 0.f,
                                 m2 ? 1.f : 0.f, m3 ? 1.f : 0.f);
        ((float4*)(out + OFF_EI))[e4]       = eis;
        ((float4*)(out + OFF_EI + EEc))[e4] = eid;
        ((float4*)(out + OFF_MASK))[e4]     = msk;
        unsigned mm = ((unsigned)m0) | ((unsigned)m1 << 1) | ((unsigned)m2 << 2) | ((unsigned)m3 << 3);
        long warpQuadBase = (long)(e4 - lane) * 16;
        const float4* eav = (const float4*)ea;
        float4* outv = (float4*)(out + OFF_EA);
#pragma unroll
        for (int half = 0; half < 4; half++) {
            int eIdx = half * 32 + lane;
            unsigned srcbits = __shfl_sync(0xffffffffu, mm, eIdx >> 2);
            bool me = (srcbits >> (eIdx & 3)) & 1u;
            unsigned bmask = __ballot_sync(0xffffffffu, me);
#pragma unroll
            for (int it = 0; it < 4; it++) {
                int tt = it * 32 + lane;
                bool keep = (bmask >> (tt >> 2)) & 1u;
                long o = warpQuadBase + (long)half * 128 + tt;
                float4 vv = make_float4(0.f, 0.f, 0.f, 0.f);
                if (keep) vv = eav[o];
                outv[o] = vv;
            }
        }
    }
}

extern "C" void kernel_launch(void* const* d_in, const int* in_sizes, int n_in,
                              void* d_out, int out_size) {
    const float* x   = (const float*)d_in[0];
    const int*   ei  = (const int*)d_in[1];
    const float* ea  = (const float*)d_in[2];
    const float* W   = (const float*)d_in[4];
    const float* b   = (const float*)d_in[5];
    float* out = (float*)d_out;

    const int* src = ei;
    const int* dst = ei + EEc;

    k_proj_deg<<<PROJ_BLOCKS + DEG_BLOCKS, 256>>>(x, W, dst);
    k_scatter <<<BB * 8, 256>>>(src, dst);
    k_topk    <<<BB, 128>>>(b, out);
    k_epilogue<<<GATHER_BLOCKS + EDGE_BLOCKS, 256>>>(x, src, dst, ea, out);
}